// round 1
// baseline (speedup 1.0000x reference)
#include <cuda_runtime.h>

// LWTA: groups of 4 consecutive floats, keep first-max, zero others.
// 4096 x 8192 fp32 -> 8,388,608 groups, one float4 per group.

__global__ void lwta_kernel(const float4* __restrict__ in,
                            float4* __restrict__ out,
                            int n_groups) {
    int i = blockIdx.x * blockDim.x + threadIdx.x;
    if (i >= n_groups) return;

    float4 v = in[i];

    // max of the 4
    float m = fmaxf(fmaxf(v.x, v.y), fmaxf(v.z, v.w));

    // first-max winner index (matches jnp.argmax tie-breaking)
    int w = (v.x == m) ? 0 : (v.y == m) ? 1 : (v.z == m) ? 2 : 3;

    float4 o;
    o.x = (w == 0) ? v.x : 0.0f;
    o.y = (w == 1) ? v.y : 0.0f;
    o.z = (w == 2) ? v.z : 0.0f;
    o.w = (w == 3) ? v.w : 0.0f;

    out[i] = o;
}

extern "C" void kernel_launch(void* const* d_in, const int* in_sizes, int n_in,
                              void* d_out, int out_size) {
    const float4* in = (const float4*)d_in[0];
    float4* out = (float4*)d_out;
    int n_groups = in_sizes[0] / 4;  // 33,554,432 / 4 = 8,388,608

    const int threads = 256;
    int blocks = (n_groups + threads - 1) / threads;
    lwta_kernel<<<blocks, threads>>>(in, out, n_groups);
}